// round 7
// baseline (speedup 1.0000x reference)
#include <cuda_runtime.h>

#define NN 256
#define BB 2
#define NNODE (BB*NN)

#define RSQRT3 0.5773502691896258f
#define INV_FAN 0.1767766952966369f   // 1/sqrt(32)

// partial G: per (node, half) -> [f*4+c], f in [0,33), f==32 = bias feature
__device__ float g_G2[2*NNODE][132];

#define PACK_F32X2(out, lo, hi) \
    asm("mov.b64 %0, {%1, %2};" : "=l"(out) : "f"(lo), "f"(hi))
#define UNPACK_F32X2(lo, hi, in) \
    asm("mov.b64 {%0, %1}, %2;" : "=f"(lo), "=f"(hi) : "l"(in))
#define FMA_F32X2(d, a, b, c) \
    asm("fma.rn.f32x2 %0, %1, %2, %3;" : "=l"(d) : "l"(a), "l"(b), "l"(c))
#define ADD_F32X2(d, a, b) \
    asm("add.rn.f32x2 %0, %1, %2;" : "=l"(d) : "l"(a), "l"(b))

#define CP_ASYNC16(dst_u32, src_ptr) \
    asm volatile("cp.async.ca.shared.global [%0], [%1], 16;" :: "r"(dst_u32), "l"(src_ptr))
#define CP_COMMIT() asm volatile("cp.async.commit_group;" ::: "memory")
#define CP_WAIT1()  asm volatile("cp.async.wait_group 1;" ::: "memory")
#define CP_WAIT0()  asm volatile("cp.async.wait_group 0;" ::: "memory")

// ---------------------------------------------------------------------------
// Kernel A: edge reduction, one block per (node, half): 128 m-rows per block.
// h[m,f] = relu(edge_attr[m,:] @ fc_w1[:,f] + fc_b1[f])
// Gpart[f,c] = sum_m h[m,f] * sh'[m,c];  Gpart[32,c] = sum_m sh'[m,c]
// ---------------------------------------------------------------------------
__global__ __launch_bounds__(256, 4) void edge_kernel(
    const float* __restrict__ edge_attr,
    const float* __restrict__ edge_sh,
    const float* __restrict__ mask,
    const float* __restrict__ fc_w1,
    const float* __restrict__ fc_b1)
{
    __shared__ __align__(16) float ea[2][64 * 32];   // 2 x 8 KB
    __shared__ __align__(16) float sh[128 * 4];      // premultiplied
    __shared__ float w1s[32 * 32];
    __shared__ float b1s[32];
    __shared__ float Gp[8][132];

    const int blk  = blockIdx.x;
    const int node = blk >> 1;
    const int half = blk & 1;
    const int b = node >> 8;
    const int n = node & 255;
    const int m0 = half * 128;
    const int t = threadIdx.x;

    const float* ea_g = edge_attr + (size_t)node * NN * 32 + (size_t)m0 * 32;
    const unsigned ea_u = (unsigned)__cvta_generic_to_shared(&ea[0][0]);

    CP_ASYNC16(ea_u + (unsigned)t * 16u, ea_g + t * 4);
    CP_ASYNC16(ea_u + 4096u + (unsigned)t * 16u, ea_g + 1024 + t * 4);
    CP_COMMIT();
    CP_ASYNC16(ea_u + 8192u + (unsigned)t * 16u, ea_g + 2048 + t * 4);
    CP_ASYNC16(ea_u + 12288u + (unsigned)t * 16u, ea_g + 3072 + t * 4);
    CP_COMMIT();

    for (int i = t; i < 1024; i += 256) w1s[i] = fc_w1[i];
    if (t < 32) b1s[t] = fc_b1[t];
    if (t < 128) {
        int m = m0 + t;
        float mf = mask[b * NN + m] * (m != n ? 1.0f : 0.0f);
        float4 s = ((const float4*)(edge_sh + (size_t)node * NN * 4))[m];
        s.x *= mf; s.y *= mf; s.z *= mf; s.w *= mf;
        ((float4*)sh)[t] = s;
    }
    __syncthreads();

    const int f  = t & 31;
    const int mg = t >> 5;

    unsigned long long w1p[16];
    #pragma unroll
    for (int j = 0; j < 16; j++)
        PACK_F32X2(w1p[j], w1s[(2*j) * 32 + f], w1s[(2*j+1) * 32 + f]);
    unsigned long long bias2;
    PACK_F32X2(bias2, b1s[f], 0.0f);

    unsigned long long acc01 = 0ULL, acc23 = 0ULL;
    const ulonglong2* sh2 = (const ulonglong2*)sh;

    #pragma unroll
    for (int ch = 0; ch < 2; ch++) {
        if (ch == 0) { CP_WAIT1(); } else { CP_WAIT0(); }
        __syncthreads();
        const float* buf = ea[ch];
        #pragma unroll
        for (int it = 0; it < 8; it++) {
            int r = mg + it * 8;
            const ulonglong2* row = (const ulonglong2*)(buf + r * 32);
            unsigned long long c0 = bias2, c1 = 0ULL;
            ulonglong2 u0 = row[0];
            ulonglong2 u1 = row[1];
            ulonglong2 u2 = row[2];
            ulonglong2 u3 = row[3];
            FMA_F32X2(c0, u0.x, w1p[0], c0);
            FMA_F32X2(c1, u0.y, w1p[1], c1);
            FMA_F32X2(c0, u1.x, w1p[2], c0);
            FMA_F32X2(c1, u1.y, w1p[3], c1);
            u0 = row[4];
            u1 = row[5];
            FMA_F32X2(c0, u2.x, w1p[4], c0);
            FMA_F32X2(c1, u2.y, w1p[5], c1);
            FMA_F32X2(c0, u3.x, w1p[6], c0);
            FMA_F32X2(c1, u3.y, w1p[7], c1);
            u2 = row[6];
            u3 = row[7];
            FMA_F32X2(c0, u0.x, w1p[8],  c0);
            FMA_F32X2(c1, u0.y, w1p[9],  c1);
            FMA_F32X2(c0, u1.x, w1p[10], c0);
            FMA_F32X2(c1, u1.y, w1p[11], c1);
            FMA_F32X2(c0, u2.x, w1p[12], c0);
            FMA_F32X2(c1, u2.y, w1p[13], c1);
            FMA_F32X2(c0, u3.x, w1p[14], c0);
            FMA_F32X2(c1, u3.y, w1p[15], c1);
            ADD_F32X2(c0, c0, c1);
            float lo, hi;
            UNPACK_F32X2(lo, hi, c0);
            float h = fmaxf(lo + hi, 0.0f);
            unsigned long long h2;
            PACK_F32X2(h2, h, h);
            ulonglong2 s2 = sh2[ch * 64 + r];
            FMA_F32X2(acc01, h2, s2.x, acc01);
            FMA_F32X2(acc23, h2, s2.y, acc23);
        }
    }

    float o0, o1, o2, o3;
    UNPACK_F32X2(o0, o1, acc01);
    UNPACK_F32X2(o2, o3, acc23);
    Gp[mg][f*4+0] = o0;
    Gp[mg][f*4+1] = o1;
    Gp[mg][f*4+2] = o2;
    Gp[mg][f*4+3] = o3;

    if (t < 32) {
        int c = t & 3, mq = t >> 2;
        float s = 0.f;
        #pragma unroll 8
        for (int m = mq; m < 128; m += 8) s += sh[m * 4 + c];
        Gp[mq][128 + c] = s;
    }
    __syncthreads();

    if (t < 132) {
        float s = 0.f;
        #pragma unroll
        for (int g = 0; g < 8; g++) s += Gp[g][t];
        g_G2[blk][t] = s;
    }
}

// ---------------------------------------------------------------------------
// Kernel B: per-node epilogue, ONE node per block, 512 blocks, 256 threads.
// W2 read directly via coalesced LDG (L1-resident across co-resident blocks).
// No cp.async pipeline, no syncs in the main loop.
// ---------------------------------------------------------------------------
__device__ __forceinline__ void pair_ldg(
    const ulonglong2* __restrict__ W, int idx,
    const float* __restrict__ Gs, int f,
    float si, float x0, float x1, float x2,
    unsigned long long accS[2], unsigned long long accV[6])
{
    ulonglong2 wss = W[idx];
    ulonglong2 wvv = W[idx + 64];
    ulonglong2 wsv = W[idx + 128];
    ulonglong2 wvs = W[idx + 192];
    float4 gv = *(const float4*)(Gs + f * 4);
    float a  = gv.x * si;
    float bc = (gv.y * x0 + gv.z * x1 + gv.w * x2) * RSQRT3;
    float c0 = gv.y * si, c1 = gv.z * si, c2 = gv.w * si;
    float d0 = gv.x * x0, d1 = gv.x * x1, d2 = gv.x * x2;
    unsigned long long a2, bc2, c02, c12, c22, d02, d12, d22;
    PACK_F32X2(a2, a, a);     PACK_F32X2(bc2, bc, bc);
    PACK_F32X2(c02, c0, c0);  PACK_F32X2(c12, c1, c1);  PACK_F32X2(c22, c2, c2);
    PACK_F32X2(d02, d0, d0);  PACK_F32X2(d12, d1, d1);  PACK_F32X2(d22, d2, d2);
    FMA_F32X2(accS[0], a2,  wss.x, accS[0]);
    FMA_F32X2(accS[1], a2,  wss.y, accS[1]);
    FMA_F32X2(accS[0], bc2, wvv.x, accS[0]);
    FMA_F32X2(accS[1], bc2, wvv.y, accS[1]);
    FMA_F32X2(accV[0], c02, wsv.x, accV[0]);
    FMA_F32X2(accV[1], c02, wsv.y, accV[1]);
    FMA_F32X2(accV[0], d02, wvs.x, accV[0]);
    FMA_F32X2(accV[1], d02, wvs.y, accV[1]);
    FMA_F32X2(accV[2], c12, wsv.x, accV[2]);
    FMA_F32X2(accV[3], c12, wsv.y, accV[3]);
    FMA_F32X2(accV[2], d12, wvs.x, accV[2]);
    FMA_F32X2(accV[3], d12, wvs.y, accV[3]);
    FMA_F32X2(accV[4], c22, wsv.x, accV[4]);
    FMA_F32X2(accV[5], c22, wsv.y, accV[5]);
    FMA_F32X2(accV[4], d22, wvs.x, accV[4]);
    FMA_F32X2(accV[5], d22, wvs.y, accV[5]);
}

__global__ __launch_bounds__(256, 3) void node_kernel(
    const float* __restrict__ node_attr,
    const float* __restrict__ mask,
    const float* __restrict__ w_lin_in_s,
    const float* __restrict__ w_lin_in_v,
    const float* __restrict__ fc_w2,
    const float* __restrict__ fc_b2,
    const float* __restrict__ w_lin_out_s,
    const float* __restrict__ w_lin_out_v,
    float* __restrict__ out)
{
    __shared__ __align__(16) float part[64 * 68];   // 17.4 KB
    __shared__ float Gs[132];
    __shared__ float sinS[16];
    __shared__ float vinS[48];
    __shared__ float wls[256], wlv[256], wos[256], wov[256];
    __shared__ float outsS[16], outvS[48];
    __shared__ float red[8];
    __shared__ float dsum_s;

    const int t = threadIdx.x;
    const int node = blockIdx.x;
    const int b = node >> 8;

    // --- prologue ---
    wls[t] = w_lin_in_s[t];
    wlv[t] = w_lin_in_v[t];
    wos[t] = w_lin_out_s[t];
    wov[t] = w_lin_out_v[t];
    if (t < 132) Gs[t] = g_G2[node * 2][t] + g_G2[node * 2 + 1][t];
    {
        float mv = mask[b * NN + t];
        #pragma unroll
        for (int o = 16; o; o >>= 1) mv += __shfl_xor_sync(0xFFFFFFFFu, mv, o);
        if ((t & 31) == 0) red[t >> 5] = mv;
    }
    __syncthreads();
    if (t == 0) {
        float s = 0.f;
        #pragma unroll
        for (int i = 0; i < 8; i++) s += red[i];
        dsum_s = s - 1.0f;
    }

    // --- s_in / v_in ---
    if (t < 64) {
        const float* na = node_attr + (size_t)node * 64;
        if (t < 16) {
            float s = 0.f;
            #pragma unroll
            for (int i = 0; i < 16; i++) s += na[i] * wls[i * 16 + t];
            sinS[t] = s * 0.25f;
        } else {
            int idx = t - 16;
            int o = idx / 3, x = idx % 3;
            float s = 0.f;
            #pragma unroll
            for (int i = 0; i < 16; i++) s += na[16 + i * 3 + x] * wlv[i * 16 + o];
            vinS[o * 3 + x] = s * 0.25f;
        }
    }
    __syncthreads();

    // --- main contraction: no syncs, direct LDG of W2 ---
    const int oq = t & 3;
    const int g  = t >> 2;     // [0,64)
    const int i  = g & 15;     // fixed per thread
    const int f0 = g >> 4;     // f = f0 + 4k

    const float si = sinS[i];
    const float x0 = vinS[i*3 + 0];
    const float x1 = vinS[i*3 + 1];
    const float x2 = vinS[i*3 + 2];

    unsigned long long accS[2] = {0ULL, 0ULL};
    unsigned long long accV[6] = {0ULL, 0ULL, 0ULL, 0ULL, 0ULL, 0ULL};

    const ulonglong2* W2 = (const ulonglong2*)fc_w2;   // [f][256] of 16B
    const int base = i * 4 + oq;
    #pragma unroll
    for (int k = 0; k < 8; k++) {
        int f = f0 + 4 * k;
        pair_ldg(W2, f * 256 + base, Gs, f, si, x0, x1, x2, accS, accV);
    }
    if (g < 16) {   // bias row f=32, i=g
        pair_ldg((const ulonglong2*)fc_b2, base, Gs, 32, si, x0, x1, x2, accS, accV);
    }

    // --- stage partials: rows 0..15 = S(o), rows 16..63 = V(o,x) ---
    #pragma unroll
    for (int h = 0; h < 2; h++) {
        float v0, v1;
        UNPACK_F32X2(v0, v1, accS[h]);
        part[(oq*4 + h*2 + 0) * 68 + g] = v0;
        part[(oq*4 + h*2 + 1) * 68 + g] = v1;
    }
    #pragma unroll
    for (int x = 0; x < 3; x++)
        #pragma unroll
        for (int h = 0; h < 2; h++) {
            float v0, v1;
            UNPACK_F32X2(v0, v1, accV[x*2 + h]);
            int o = oq*4 + h*2;
            part[(16 + o*3 + x) * 68 + g] = v0;
            part[(16 + (o+1)*3 + x) * 68 + g] = v1;
        }
    __syncthreads();

    // --- reduce over 64 groups, apply scale ---
    if (t < 64) {
        float scale = INV_FAN / dsum_s;
        const float4* row = (const float4*)(part + t * 68);
        float s = 0.f;
        #pragma unroll
        for (int j = 0; j < 16; j++) {
            float4 v = row[j];
            s += (v.x + v.y) + (v.z + v.w);
        }
        if (t < 16) outsS[t] = s * scale;
        else        outvS[t - 16] = s * scale;
    }
    __syncthreads();

    // --- output linear (/4) + residual ---
    if (t < 64) {
        const float* na = node_attr + (size_t)node * 64;
        float r;
        if (t < 16) {
            float s = 0.f;
            #pragma unroll
            for (int o = 0; o < 16; o++) s += outsS[o] * wos[o * 16 + t];
            r = s * 0.25f + na[t];
        } else {
            int idx = t - 16;
            int o2 = idx / 3, x = idx % 3;
            float s = 0.f;
            #pragma unroll
            for (int o = 0; o < 16; o++) s += outvS[o * 3 + x] * wov[o * 16 + o2];
            r = s * 0.25f + na[t];
        }
        out[(size_t)node * 64 + t] = r;
    }
}

extern "C" void kernel_launch(void* const* d_in, const int* in_sizes, int n_in,
                              void* d_out, int out_size) {
    const float* node_attr    = (const float*)d_in[0];
    const float* edge_attr    = (const float*)d_in[1];
    const float* edge_sh      = (const float*)d_in[2];
    const float* mask         = (const float*)d_in[3];
    const float* w_lin_in_s   = (const float*)d_in[4];
    const float* w_lin_in_v   = (const float*)d_in[5];
    const float* fc_w1        = (const float*)d_in[6];
    const float* fc_b1        = (const float*)d_in[7];
    const float* fc_w2        = (const float*)d_in[8];
    const float* fc_b2        = (const float*)d_in[9];
    const float* w_lin_out_s  = (const float*)d_in[10];
    const float* w_lin_out_v  = (const float*)d_in[11];
    float* out = (float*)d_out;

    edge_kernel<<<2 * NNODE, 256>>>(edge_attr, edge_sh, mask, fc_w1, fc_b1);
    node_kernel<<<NNODE, 256>>>(node_attr, mask, w_lin_in_s, w_lin_in_v,
                                fc_w2, fc_b2, w_lin_out_s, w_lin_out_v, out);
}